// round 1
// baseline (speedup 1.0000x reference)
#include <cuda_runtime.h>
#include <cstdint>

#define BB 256
#define TT 2048
#define HH 64

typedef unsigned long long u64;

// ---------- scratch (module-load allocated, allowed) ----------
__device__ float g_out1[(size_t)BB * TT * 128];        // layer-1 output [B,T,128] (fwd|bwd)
__device__ float g_pre2[(size_t)BB * TT * 256];        // layer-2 input preactivations [B,T,4H]

// ---------- packed fp32x2 helpers (sm_103a FFMA2) ----------
__device__ __forceinline__ u64 ffma2(u64 a, u64 b, u64 c) {
    u64 d;
    asm("fma.rn.f32x2 %0, %1, %2, %3;" : "=l"(d) : "l"(a), "l"(b), "l"(c));
    return d;
}
__device__ __forceinline__ float2 uf2(u64 v) {
    float2 r;
    asm("mov.b64 {%0, %1}, %2;" : "=f"(r.x), "=f"(r.y) : "l"(v));
    return r;
}

// ---------- fast activations (fp32, MUFU-based) ----------
__device__ __forceinline__ float sigmoid_(float x) {
    float e = __expf(-x);
    return __fdividef(1.f, 1.f + e);
}
__device__ __forceinline__ float tanh_(float x) {
    float e = __expf(2.f * x);              // +inf / 0 extremes handled below
    return 1.f - __fdividef(2.f, e + 1.f);  // inf -> 1, 0 -> -1
}

// =====================================================================
// Layer-1 scan: one block per (sample, direction). 256 threads = 1 gate each.
// gate pre = b[g] + Wih[g,:]·x_t + Whh[g,:]·h   (Whh row held in regs as f32x2)
// =====================================================================
__global__ __launch_bounds__(256, 2)
void l1_scan(const float* __restrict__ x,
             const float* __restrict__ Wih_f, const float* __restrict__ Whh_f, const float* __restrict__ b_f,
             const float* __restrict__ Wih_b, const float* __restrict__ Whh_b, const float* __restrict__ b_b)
{
    const int s   = blockIdx.x & (BB - 1);
    const int dir = blockIdx.x >> 8;           // 0 = fwd, 1 = bwd
    const int g   = threadIdx.x;               // gate index [0,256)

    const float* Wih = dir ? Wih_b : Wih_f;
    const float* Whh = dir ? Whh_b : Whh_f;
    const float* bv  = dir ? b_b   : b_f;

    // recurrent weight row -> 32 packed f32x2 registers
    u64 w[32];
    const u64* wrow = (const u64*)(Whh + g * HH);
#pragma unroll
    for (int k = 0; k < 32; k++) w[k] = wrow[k];

    const float wi0 = Wih[g * 4 + 0], wi1 = Wih[g * 4 + 1];
    const float wi2 = Wih[g * 4 + 2], wi3 = Wih[g * 4 + 3];
    const float bias = bv[g];

    __shared__ u64  sh2[32];         // h as 32 packed pairs
    __shared__ float sact[256];      // activated gates
    float* shf = (float*)sh2;

    if (g < 32) sh2[g] = 0ull;       // h0 = 0
    float c = 0.f;
    __syncthreads();

    const float4* xrow = (const float4*)(x + (size_t)s * TT * 4);
    float* orow = g_out1 + (size_t)s * TT * 128 + dir * HH;

    for (int t = 0; t < TT; t++) {
        const int tt = dir ? (TT - 1 - t) : t;
        const float4 xv = __ldg(xrow + tt);

        u64 a0 = 0ull, a1 = 0ull, a2 = 0ull, a3 = 0ull;
#pragma unroll
        for (int k = 0; k < 32; k += 4) {
            a0 = ffma2(w[k + 0], sh2[k + 0], a0);
            a1 = ffma2(w[k + 1], sh2[k + 1], a1);
            a2 = ffma2(w[k + 2], sh2[k + 2], a2);
            a3 = ffma2(w[k + 3], sh2[k + 3], a3);
        }
        float2 r0 = uf2(a0), r1 = uf2(a1), r2 = uf2(a2), r3 = uf2(a3);
        float pre = ((r0.x + r0.y) + (r1.x + r1.y)) + ((r2.x + r2.y) + (r3.x + r3.y))
                  + bias + wi0 * xv.x + wi1 * xv.y + wi2 * xv.z + wi3 * xv.w;

        float a = (g >= 128 && g < 192) ? tanh_(pre) : sigmoid_(pre);
        sact[g] = a;
        __syncthreads();

        if (g < HH) {
            float iv = sact[g], fv = sact[64 + g], gv = sact[128 + g], ov = sact[192 + g];
            c = fv * c + iv * gv;
            float h = ov * tanh_(c);
            shf[g] = h;
            orow[(size_t)tt * 128 + g] = h;
        }
        __syncthreads();
    }
}

// =====================================================================
// pre2 GEMM: g_pre2[m, g] = sum_k g_out1[m, k] * Wih2[g, k] + b2[g]
// M = B*T = 524288, K = 128, N = 256. W row (128 fp32) held in regs per thread.
// Block: 64 rows, A tile staged in SMEM, broadcast reads.
// =====================================================================
__global__ __launch_bounds__(256, 1)
void pre2_gemm(const float* __restrict__ Wih2, const float* __restrict__ b2)
{
    const int g  = threadIdx.x;
    const int m0 = blockIdx.x * 64;

    u64 w[64];
    const u64* wrow = (const u64*)(Wih2 + (size_t)g * 128);
#pragma unroll
    for (int k = 0; k < 64; k++) w[k] = wrow[k];
    const float bias = b2[g];

    __shared__ float As[64 * 128];   // 32 KB

    // cooperative tile load (coalesced float4)
    const float4* src = (const float4*)(g_out1 + (size_t)m0 * 128);
    float4* dst = (float4*)As;
#pragma unroll
    for (int i = 0; i < 8; i++) dst[g + i * 256] = src[g + i * 256];
    __syncthreads();

    float* out = g_pre2 + (size_t)m0 * 256 + g;
    for (int m = 0; m < 64; m++) {
        const ulonglong2* arow = (const ulonglong2*)(As + m * 128);
        u64 a0 = 0ull, a1 = 0ull, a2 = 0ull, a3 = 0ull;
#pragma unroll
        for (int k = 0; k < 16; k++) {
            ulonglong2 v0 = arow[2 * k];
            ulonglong2 v1 = arow[2 * k + 1];
            a0 = ffma2(w[4 * k + 0], v0.x, a0);
            a1 = ffma2(w[4 * k + 1], v0.y, a1);
            a2 = ffma2(w[4 * k + 2], v1.x, a2);
            a3 = ffma2(w[4 * k + 3], v1.y, a3);
        }
        float2 r0 = uf2(a0), r1 = uf2(a1), r2 = uf2(a2), r3 = uf2(a3);
        float val = ((r0.x + r0.y) + (r1.x + r1.y)) + ((r2.x + r2.y) + (r3.x + r3.y)) + bias;
        out[(size_t)m * 256] = val;
    }
}

// =====================================================================
// Layer-2 scan: one block per sample, recurrent K=64 only (input preact
// streamed from g_pre2 with depth-2 register prefetch). Fused FC epilogue.
// =====================================================================
__global__ __launch_bounds__(256, 2)
void l2_scan(const float* __restrict__ Whh2,
             const float* __restrict__ Wfc, const float* __restrict__ bfc,
             float* __restrict__ out)
{
    const int s = blockIdx.x;
    const int g = threadIdx.x;

    u64 w[32];
    const u64* wrow = (const u64*)(Whh2 + g * HH);
#pragma unroll
    for (int k = 0; k < 32; k++) w[k] = wrow[k];

    __shared__ u64  sh2[32];
    __shared__ float sact[256];
    __shared__ float sred[64];
    float* shf = (float*)sh2;

    if (g < 32) sh2[g] = 0ull;
    float c = 0.f;
    __syncthreads();

    const float* prow = g_pre2 + (size_t)s * TT * 256 + g;
    float p_cur = __ldg(prow);
    float p_nx1 = __ldg(prow + 256);

    for (int t = 0; t < TT; t++) {
        float p_nx2 = (t + 2 < TT) ? __ldg(prow + (size_t)(t + 2) * 256) : 0.f;

        u64 a0 = 0ull, a1 = 0ull, a2 = 0ull, a3 = 0ull;
#pragma unroll
        for (int k = 0; k < 32; k += 4) {
            a0 = ffma2(w[k + 0], sh2[k + 0], a0);
            a1 = ffma2(w[k + 1], sh2[k + 1], a1);
            a2 = ffma2(w[k + 2], sh2[k + 2], a2);
            a3 = ffma2(w[k + 3], sh2[k + 3], a3);
        }
        float2 r0 = uf2(a0), r1 = uf2(a1), r2 = uf2(a2), r3 = uf2(a3);
        float pre = ((r0.x + r0.y) + (r1.x + r1.y)) + ((r2.x + r2.y) + (r3.x + r3.y)) + p_cur;

        float a = (g >= 128 && g < 192) ? tanh_(pre) : sigmoid_(pre);
        sact[g] = a;
        __syncthreads();

        if (g < HH) {
            float iv = sact[g], fv = sact[64 + g], gv = sact[128 + g], ov = sact[192 + g];
            c = fv * c + iv * gv;
            shf[g] = ov * tanh_(c);
        }
        __syncthreads();

        p_cur = p_nx1;
        p_nx1 = p_nx2;
    }

    // fused FC: logits[s] = Wfc · h_T + bfc
    if (g < HH) sred[g] = shf[g] * __ldg(Wfc + g);
    __syncthreads();
    if (g == 0) {
        float acc = __ldg(bfc);
#pragma unroll
        for (int j = 0; j < HH; j++) acc += sred[j];
        out[s] = acc;
    }
}

// =====================================================================
extern "C" void kernel_launch(void* const* d_in, const int* in_sizes, int n_in,
                              void* d_out, int out_size)
{
    const float* x     = (const float*)d_in[0];
    const float* Wih_f = (const float*)d_in[1];
    const float* Whh_f = (const float*)d_in[2];
    const float* b_f   = (const float*)d_in[3];
    const float* Wih_b = (const float*)d_in[4];
    const float* Whh_b = (const float*)d_in[5];
    const float* b_b   = (const float*)d_in[6];
    const float* Wih2  = (const float*)d_in[7];
    const float* Whh2  = (const float*)d_in[8];
    const float* b2    = (const float*)d_in[9];
    const float* Wfc   = (const float*)d_in[10];
    const float* bfc   = (const float*)d_in[11];
    float* out = (float*)d_out;

    l1_scan<<<512, 256>>>(x, Wih_f, Whh_f, b_f, Wih_b, Whh_b, b_b);
    pre2_gemm<<<(BB * TT) / 64, 256>>>(Wih2, b2);
    l2_scan<<<BB, 256>>>(Whh2, Wfc, bfc, out);
}

// round 2
// speedup vs baseline: 1.2624x; 1.2624x over previous
#include <cuda_runtime.h>
#include <mma.h>
#include <cstdint>

#define BB 256
#define TT 2048
#define HH 64

typedef unsigned long long u64;
using namespace nvcuda;

// ---------- scratch ----------
__device__ float g_out1[(size_t)BB * TT * 128];   // layer-1 output [B,T,128] (fwd|bwd)
__device__ float g_pre2[(size_t)BB * TT * 256];   // layer-2 input preact (NO bias) [B,T,4H]

// ---------- packed fp32x2 (sm_103a FFMA2) ----------
__device__ __forceinline__ u64 ffma2(u64 a, u64 b, u64 c) {
    u64 d; asm("fma.rn.f32x2 %0, %1, %2, %3;" : "=l"(d) : "l"(a), "l"(b), "l"(c)); return d;
}
__device__ __forceinline__ u64 fadd2(u64 a, u64 b) {
    u64 d; asm("add.rn.f32x2 %0, %1, %2;" : "=l"(d) : "l"(a), "l"(b)); return d;
}
__device__ __forceinline__ float2 uf2(u64 v) {
    float2 r; asm("mov.b64 {%0, %1}, %2;" : "=f"(r.x), "=f"(r.y) : "l"(v)); return r;
}

// ---------- MUFU.TANH activations ----------
__device__ __forceinline__ float tanh_f(float x) {
    float y; asm("tanh.approx.f32 %0, %1;" : "=f"(y) : "f"(x)); return y;
}
__device__ __forceinline__ float sigmoid_f(float x) {
    return fmaf(tanh_f(0.5f * x), 0.5f, 0.5f);
}

// =====================================================================
// Layer-1 scan: one block per (sample, direction). 256 threads = 1 gate each.
// =====================================================================
__global__ __launch_bounds__(256, 2)
void l1_scan(const float* __restrict__ x,
             const float* __restrict__ Wih_f, const float* __restrict__ Whh_f, const float* __restrict__ b_f,
             const float* __restrict__ Wih_b, const float* __restrict__ Whh_b, const float* __restrict__ b_b)
{
    const int s   = blockIdx.x & (BB - 1);
    const int dir = blockIdx.x >> 8;
    const int g   = threadIdx.x;

    const float* Wih = dir ? Wih_b : Wih_f;
    const float* Whh = dir ? Whh_b : Whh_f;
    const float* bv  = dir ? b_b   : b_f;

    u64 w[32];
    const u64* wrow = (const u64*)(Whh + g * HH);
#pragma unroll
    for (int k = 0; k < 32; k++) w[k] = wrow[k];

    const float wi0 = Wih[g * 4 + 0], wi1 = Wih[g * 4 + 1];
    const float wi2 = Wih[g * 4 + 2], wi3 = Wih[g * 4 + 3];
    const float bias = bv[g];

    __shared__ u64  sh2[32];
    __shared__ float sact[256];
    float* shf = (float*)sh2;

    if (g < 32) sh2[g] = 0ull;
    float c = 0.f;
    __syncthreads();

    const int step = dir ? -1 : 1;
    const float4* xptr = (const float4*)(x + (size_t)s * TT * 4) + (dir ? TT - 1 : 0);
    float* optr = g_out1 + (size_t)s * TT * 128 + dir * HH + (dir ? (size_t)(TT - 1) * 128 : 0);

    // depth-2 prefetch of x
    float4 xv0 = __ldg(xptr);
    float4 xv1 = __ldg(xptr + step);

    for (int t = 0; t < TT; t++) {
        float4 xv2 = (t + 2 < TT) ? __ldg(xptr + 2 * step) : make_float4(0.f, 0.f, 0.f, 0.f);

        u64 a0 = 0ull, a1 = 0ull, a2 = 0ull, a3 = 0ull;
#pragma unroll
        for (int k = 0; k < 32; k += 4) {
            a0 = ffma2(w[k + 0], sh2[k + 0], a0);
            a1 = ffma2(w[k + 1], sh2[k + 1], a1);
            a2 = ffma2(w[k + 2], sh2[k + 2], a2);
            a3 = ffma2(w[k + 3], sh2[k + 3], a3);
        }
        u64 ss = fadd2(fadd2(a0, a1), fadd2(a2, a3));
        float2 r = uf2(ss);
        float pre = (r.x + r.y) + bias
                  + wi0 * xv0.x + wi1 * xv0.y + wi2 * xv0.z + wi3 * xv0.w;

        float a = (g >= 128 && g < 192) ? tanh_f(pre) : sigmoid_f(pre);
        sact[g] = a;
        __syncthreads();

        if (g < HH) {
            float iv = sact[g], fv = sact[64 + g], gv = sact[128 + g], ov = sact[192 + g];
            c = fv * c + iv * gv;
            float h = ov * tanh_f(c);
            shf[g] = h;
            optr[g] = h;
        }
        __syncthreads();

        xv0 = xv1; xv1 = xv2;
        xptr += step;
        optr += step * 128;
    }
}

// =====================================================================
// pre2 GEMM (tf32 WMMA): g_pre2[m, n] = sum_k g_out1[m, k] * Wih2[n, k]
// M = 524288, K = 128, N = 256. Tile: 64 rows/block. Bias added in l2_scan.
// Warp w owns n-tiles {2w, 2w+1}; B fragments register-resident across m.
// =====================================================================
__global__ __launch_bounds__(256, 2)
void pre2_wmma(const float* __restrict__ Wih2)
{
    const int w  = threadIdx.x >> 5;
    const int m0 = blockIdx.x * 64;

    __shared__ float As[64 * 136];   // 34.8 KB, padded rows

    // cooperative A-tile load: 64 rows x 32 float4
    {
        const float4* src = (const float4*)(g_out1 + (size_t)m0 * 128);
        for (int i = threadIdx.x; i < 64 * 32; i += 256) {
            int rr = i >> 5, cc = i & 31;
            *(float4*)&As[rr * 136 + cc * 4] = src[i];
        }
    }
    __syncthreads();

#pragma unroll 1
    for (int half = 0; half < 2; half++) {
        const int n0 = (w * 2 + half) * 16;

        wmma::fragment<wmma::matrix_b, 16, 16, 8, wmma::precision::tf32, wmma::col_major> bf[16];
#pragma unroll
        for (int k = 0; k < 16; k++) {
            wmma::load_matrix_sync(bf[k], Wih2 + (size_t)n0 * 128 + k * 8, 128);
#pragma unroll
            for (int e = 0; e < bf[k].num_elements; e++)
                bf[k].x[e] = wmma::__float_to_tf32(bf[k].x[e]);
        }

#pragma unroll 1
        for (int m = 0; m < 4; m++) {
            wmma::fragment<wmma::accumulator, 16, 16, 8, float> acc;
            wmma::fill_fragment(acc, 0.f);
#pragma unroll
            for (int k = 0; k < 16; k++) {
                wmma::fragment<wmma::matrix_a, 16, 16, 8, wmma::precision::tf32, wmma::row_major> af;
                wmma::load_matrix_sync(af, &As[(m * 16) * 136 + k * 8], 136);
#pragma unroll
                for (int e = 0; e < af.num_elements; e++)
                    af.x[e] = wmma::__float_to_tf32(af.x[e]);
                wmma::mma_sync(acc, af, bf[k], acc);
            }
            wmma::store_matrix_sync(g_pre2 + (size_t)(m0 + m * 16) * 256 + n0, acc, 256,
                                    wmma::mem_row_major);
        }
    }
}

// =====================================================================
// Layer-2 scan: one block per sample. Bias b2 fused here. Fused FC epilogue.
// =====================================================================
__global__ __launch_bounds__(256, 2)
void l2_scan(const float* __restrict__ Whh2, const float* __restrict__ b2,
             const float* __restrict__ Wfc, const float* __restrict__ bfc,
             float* __restrict__ out)
{
    const int s = blockIdx.x;
    const int g = threadIdx.x;

    u64 w[32];
    const u64* wrow = (const u64*)(Whh2 + g * HH);
#pragma unroll
    for (int k = 0; k < 32; k++) w[k] = wrow[k];
    const float bias = b2[g];

    __shared__ u64  sh2[32];
    __shared__ float sact[256];
    __shared__ float sred[64];
    float* shf = (float*)sh2;

    if (g < 32) sh2[g] = 0ull;
    float c = 0.f;
    __syncthreads();

    const float* prow = g_pre2 + (size_t)s * TT * 256 + g;
    // depth-3 prefetch to cover DRAM latency
    float p0 = __ldg(prow);
    float p1 = __ldg(prow + 256);
    float p2 = __ldg(prow + 512);

    for (int t = 0; t < TT; t++) {
        float p3 = (t + 3 < TT) ? __ldg(prow + (size_t)(t + 3) * 256) : 0.f;

        u64 a0 = 0ull, a1 = 0ull, a2 = 0ull, a3 = 0ull;
#pragma unroll
        for (int k = 0; k < 32; k += 4) {
            a0 = ffma2(w[k + 0], sh2[k + 0], a0);
            a1 = ffma2(w[k + 1], sh2[k + 1], a1);
            a2 = ffma2(w[k + 2], sh2[k + 2], a2);
            a3 = ffma2(w[k + 3], sh2[k + 3], a3);
        }
        u64 ss = fadd2(fadd2(a0, a1), fadd2(a2, a3));
        float2 r = uf2(ss);
        float pre = (r.x + r.y) + p0 + bias;

        float a = (g >= 128 && g < 192) ? tanh_f(pre) : sigmoid_f(pre);
        sact[g] = a;
        __syncthreads();

        if (g < HH) {
            float iv = sact[g], fv = sact[64 + g], gv = sact[128 + g], ov = sact[192 + g];
            c = fv * c + iv * gv;
            shf[g] = ov * tanh_f(c);
        }
        __syncthreads();

        p0 = p1; p1 = p2; p2 = p3;
    }

    if (g < HH) sred[g] = shf[g] * __ldg(Wfc + g);
    __syncthreads();
    if (g == 0) {
        float acc = __ldg(bfc);
#pragma unroll
        for (int j = 0; j < HH; j++) acc += sred[j];
        out[s] = acc;
    }
}

// =====================================================================
extern "C" void kernel_launch(void* const* d_in, const int* in_sizes, int n_in,
                              void* d_out, int out_size)
{
    const float* x     = (const float*)d_in[0];
    const float* Wih_f = (const float*)d_in[1];
    const float* Whh_f = (const float*)d_in[2];
    const float* b_f   = (const float*)d_in[3];
    const float* Wih_b = (const float*)d_in[4];
    const float* Whh_b = (const float*)d_in[5];
    const float* b_b   = (const float*)d_in[6];
    const float* Wih2  = (const float*)d_in[7];
    const float* Whh2  = (const float*)d_in[8];
    const float* b2    = (const float*)d_in[9];
    const float* Wfc   = (const float*)d_in[10];
    const float* bfc   = (const float*)d_in[11];
    float* out = (float*)d_out;

    l1_scan<<<512, 256>>>(x, Wih_f, Whh_f, b_f, Wih_b, Whh_b, b_b);
    pre2_wmma<<<(BB * TT) / 64, 256>>>(Wih2);
    l2_scan<<<BB, 256>>>(Whh2, b2, Wfc, bfc, out);
}

// round 3
// speedup vs baseline: 1.3554x; 1.0737x over previous
#include <cuda_runtime.h>
#include <mma.h>
#include <cstdint>

#define BB 256
#define TT 2048
#define HH 64

typedef unsigned long long u64;
using namespace nvcuda;

// ---------- scratch ----------
__device__ float g_out1[(size_t)BB * TT * 128];   // layer-1 output [B,T,128] (fwd|bwd)
__device__ float g_pre2[(size_t)BB * TT * 256];   // layer-2 input preact (NO bias) [B,T,4H]

// ---------- packed fp32x2 (sm_103a FFMA2) ----------
__device__ __forceinline__ u64 ffma2(u64 a, u64 b, u64 c) {
    u64 d; asm("fma.rn.f32x2 %0, %1, %2, %3;" : "=l"(d) : "l"(a), "l"(b), "l"(c)); return d;
}
__device__ __forceinline__ u64 fadd2(u64 a, u64 b) {
    u64 d; asm("add.rn.f32x2 %0, %1, %2;" : "=l"(d) : "l"(a), "l"(b)); return d;
}
__device__ __forceinline__ float2 uf2(u64 v) {
    float2 r; asm("mov.b64 {%0, %1}, %2;" : "=f"(r.x), "=f"(r.y) : "l"(v)); return r;
}

// ---------- MUFU.TANH activations ----------
__device__ __forceinline__ float tanh_f(float x) {
    float y; asm("tanh.approx.f32 %0, %1;" : "=f"(y) : "f"(x)); return y;
}
__device__ __forceinline__ float sigmoid_f(float x) {
    return fmaf(tanh_f(0.5f * x), 0.5f, 0.5f);
}

// =====================================================================
// Layer-1 scan: one block per (sample-pair, direction).
// 256 threads = 1 gate each, serving TWO samples (weights shared in regs).
// =====================================================================
__global__ __launch_bounds__(256, 2)
void l1_scan(const float* __restrict__ x,
             const float* __restrict__ Wih_f, const float* __restrict__ Whh_f, const float* __restrict__ b_f,
             const float* __restrict__ Wih_b, const float* __restrict__ Whh_b, const float* __restrict__ b_b)
{
    const int pair = blockIdx.x & 127;     // 128 sample pairs
    const int dir  = blockIdx.x >> 7;      // 0 fwd, 1 bwd
    const int s0   = pair * 2;
    const int g    = threadIdx.x;

    const float* Wih = dir ? Wih_b : Wih_f;
    const float* Whh = dir ? Whh_b : Whh_f;
    const float* bv  = dir ? b_b   : b_f;

    u64 w[32];
    const u64* wrow = (const u64*)(Whh + g * HH);
#pragma unroll
    for (int k = 0; k < 32; k++) w[k] = wrow[k];

    const float4 wi = *(const float4*)(Wih + g * 4);
    const float bias = bv[g];

    __shared__ float hs[2][64];
    __shared__ float sact[2][256];

    if (g < 128) hs[g >> 6][g & 63] = 0.f;
    float c = 0.f;
    __syncthreads();

    const int step = dir ? -1 : 1;
    const int t0   = dir ? TT - 1 : 0;
    const float4* xp0 = (const float4*)(x + (size_t)s0 * TT * 4) + t0;
    const float4* xp1 = (const float4*)(x + (size_t)(s0 + 1) * TT * 4) + t0;

    float* optr = nullptr;
    if (g < 128) {
        int smp = g >> 6, j = g & 63;
        optr = g_out1 + (size_t)(s0 + smp) * TT * 128 + (size_t)t0 * 128 + dir * HH + j;
    }

    // depth-2 x prefetch
    float4 xa0 = __ldg(xp0), xa1 = __ldg(xp0 + step);
    float4 xb0 = __ldg(xp1), xb1 = __ldg(xp1 + step);

    for (int t = 0; t < TT; t++) {
        float4 xa2, xb2;
        if (t + 2 < TT) { xa2 = __ldg(xp0 + 2 * step); xb2 = __ldg(xp1 + 2 * step); }
        else            { xa2 = make_float4(0.f,0.f,0.f,0.f); xb2 = xa2; }

        const ulonglong2* H0 = (const ulonglong2*)hs[0];
        const ulonglong2* H1 = (const ulonglong2*)hs[1];
        u64 a0=0ull,a1=0ull,a2=0ull,a3=0ull;
        u64 d0=0ull,d1=0ull,d2=0ull,d3=0ull;
#pragma unroll
        for (int k = 0; k < 16; k += 2) {
            ulonglong2 v0 = H0[k],     u0 = H1[k];
            ulonglong2 v1 = H0[k + 1], u1 = H1[k + 1];
            a0 = ffma2(w[2*k + 0], v0.x, a0);
            a1 = ffma2(w[2*k + 1], v0.y, a1);
            d0 = ffma2(w[2*k + 0], u0.x, d0);
            d1 = ffma2(w[2*k + 1], u0.y, d1);
            a2 = ffma2(w[2*k + 2], v1.x, a2);
            a3 = ffma2(w[2*k + 3], v1.y, a3);
            d2 = ffma2(w[2*k + 2], u1.x, d2);
            d3 = ffma2(w[2*k + 3], u1.y, d3);
        }
        float2 ra = uf2(fadd2(fadd2(a0, a1), fadd2(a2, a3)));
        float2 rb = uf2(fadd2(fadd2(d0, d1), fadd2(d2, d3)));
        float pre0 = (ra.x + ra.y) + bias
                   + wi.x * xa0.x + wi.y * xa0.y + wi.z * xa0.z + wi.w * xa0.w;
        float pre1 = (rb.x + rb.y) + bias
                   + wi.x * xb0.x + wi.y * xb0.y + wi.z * xb0.z + wi.w * xb0.w;

        const bool isg = (g >= 128 && g < 192);
        sact[0][g] = isg ? tanh_f(pre0) : sigmoid_f(pre0);
        sact[1][g] = isg ? tanh_f(pre1) : sigmoid_f(pre1);
        __syncthreads();

        if (g < 128) {
            const int smp = g >> 6, j = g & 63;
            float iv = sact[smp][j],       fv = sact[smp][64 + j];
            float gv = sact[smp][128 + j], ov = sact[smp][192 + j];
            c = fv * c + iv * gv;
            float h = ov * tanh_f(c);
            hs[smp][j] = h;
            *optr = h;
            optr += step * 128;
        }
        __syncthreads();

        xa0 = xa1; xa1 = xa2; xb0 = xb1; xb1 = xb2;
        xp0 += step; xp1 += step;
    }
}

// =====================================================================
// pre2 GEMM (tf32 WMMA): g_pre2[m, n] = sum_k g_out1[m, k] * Wih2[n, k]
// A-tile pre-truncated to tf32 during the smem load (no in-loop converts).
// =====================================================================
__global__ __launch_bounds__(256, 2)
void pre2_wmma(const float* __restrict__ Wih2)
{
    const int w  = threadIdx.x >> 5;
    const int m0 = blockIdx.x * 64;

    __shared__ float As[64 * 136];

    {
        const float4* src = (const float4*)(g_out1 + (size_t)m0 * 128);
        for (int i = threadIdx.x; i < 64 * 32; i += 256) {
            int rr = i >> 5, cc = i & 31;
            float4 v = src[i];
            v.x = wmma::__float_to_tf32(v.x);
            v.y = wmma::__float_to_tf32(v.y);
            v.z = wmma::__float_to_tf32(v.z);
            v.w = wmma::__float_to_tf32(v.w);
            *(float4*)&As[rr * 136 + cc * 4] = v;
        }
    }
    __syncthreads();

#pragma unroll 1
    for (int half = 0; half < 2; half++) {
        const int n0 = (w * 2 + half) * 16;

        wmma::fragment<wmma::matrix_b, 16, 16, 8, wmma::precision::tf32, wmma::col_major> bf[16];
#pragma unroll
        for (int k = 0; k < 16; k++) {
            wmma::load_matrix_sync(bf[k], Wih2 + (size_t)n0 * 128 + k * 8, 128);
#pragma unroll
            for (int e = 0; e < bf[k].num_elements; e++)
                bf[k].x[e] = wmma::__float_to_tf32(bf[k].x[e]);
        }

#pragma unroll 1
        for (int m = 0; m < 4; m++) {
            wmma::fragment<wmma::accumulator, 16, 16, 8, float> acc;
            wmma::fill_fragment(acc, 0.f);
#pragma unroll
            for (int k = 0; k < 16; k++) {
                wmma::fragment<wmma::matrix_a, 16, 16, 8, wmma::precision::tf32, wmma::row_major> af;
                wmma::load_matrix_sync(af, &As[(m * 16) * 136 + k * 8], 136);
                wmma::mma_sync(acc, af, bf[k], acc);
            }
            wmma::store_matrix_sync(g_pre2 + (size_t)(m0 + m * 16) * 256 + n0, acc, 256,
                                    wmma::mem_row_major);
        }
    }
}

// =====================================================================
// Layer-2 scan: one block per sample (1 wave already). LDS.128 matvec.
// =====================================================================
__global__ __launch_bounds__(256, 2)
void l2_scan(const float* __restrict__ Whh2, const float* __restrict__ b2,
             const float* __restrict__ Wfc, const float* __restrict__ bfc,
             float* __restrict__ out)
{
    const int s = blockIdx.x;
    const int g = threadIdx.x;

    u64 w[32];
    const u64* wrow = (const u64*)(Whh2 + g * HH);
#pragma unroll
    for (int k = 0; k < 32; k++) w[k] = wrow[k];
    const float bias = b2[g];

    __shared__ float hsf[64];
    __shared__ float sact[256];
    __shared__ float sred[64];

    if (g < 64) hsf[g] = 0.f;
    float c = 0.f;
    __syncthreads();

    const float* prow = g_pre2 + (size_t)s * TT * 256 + g;
    float p0 = __ldg(prow);
    float p1 = __ldg(prow + 256);
    float p2 = __ldg(prow + 512);

    for (int t = 0; t < TT; t++) {
        float p3 = (t + 3 < TT) ? __ldg(prow + (size_t)(t + 3) * 256) : 0.f;

        const ulonglong2* H = (const ulonglong2*)hsf;
        u64 a0=0ull,a1=0ull,a2=0ull,a3=0ull;
#pragma unroll
        for (int k = 0; k < 16; k += 2) {
            ulonglong2 v0 = H[k], v1 = H[k + 1];
            a0 = ffma2(w[2*k + 0], v0.x, a0);
            a1 = ffma2(w[2*k + 1], v0.y, a1);
            a2 = ffma2(w[2*k + 2], v1.x, a2);
            a3 = ffma2(w[2*k + 3], v1.y, a3);
        }
        float2 r = uf2(fadd2(fadd2(a0, a1), fadd2(a2, a3)));
        float pre = (r.x + r.y) + p0 + bias;

        float a = (g >= 128 && g < 192) ? tanh_f(pre) : sigmoid_f(pre);
        sact[g] = a;
        __syncthreads();

        if (g < HH) {
            float iv = sact[g], fv = sact[64 + g], gv = sact[128 + g], ov = sact[192 + g];
            c = fv * c + iv * gv;
            hsf[g] = ov * tanh_f(c);
        }
        __syncthreads();

        p0 = p1; p1 = p2; p2 = p3;
    }

    if (g < HH) sred[g] = hsf[g] * __ldg(Wfc + g);
    __syncthreads();
    if (g == 0) {
        float acc = __ldg(bfc);
#pragma unroll
        for (int j = 0; j < HH; j++) acc += sred[j];
        out[s] = acc;
    }
}

// =====================================================================
extern "C" void kernel_launch(void* const* d_in, const int* in_sizes, int n_in,
                              void* d_out, int out_size)
{
    const float* x     = (const float*)d_in[0];
    const float* Wih_f = (const float*)d_in[1];
    const float* Whh_f = (const float*)d_in[2];
    const float* b_f   = (const float*)d_in[3];
    const float* Wih_b = (const float*)d_in[4];
    const float* Whh_b = (const float*)d_in[5];
    const float* b_b   = (const float*)d_in[6];
    const float* Wih2  = (const float*)d_in[7];
    const float* Whh2  = (const float*)d_in[8];
    const float* b2    = (const float*)d_in[9];
    const float* Wfc   = (const float*)d_in[10];
    const float* bfc   = (const float*)d_in[11];
    float* out = (float*)d_out;

    l1_scan<<<256, 256>>>(x, Wih_f, Whh_f, b_f, Wih_b, Whh_b, b_b);
    pre2_wmma<<<(BB * TT) / 64, 256>>>(Wih2);
    l2_scan<<<BB, 256>>>(Whh2, b2, Wfc, bfc, out);
}